// round 1
// baseline (speedup 1.0000x reference)
#include <cuda_runtime.h>
#include <cuda_bf16.h>
#include <math.h>

// Problem constants
#define BF      96          // B * MAX_FRAMES
#define NTOK    197
#define NSP     196
#define DIM     512
#define HID     256
#define TOPK    49
#define NS      256
#define SIGMA   0.05f
#define M1      (BF*NTOK)   // 18912 rows for GEMM1
#define M3      (BF*NSP)    // 18816 rows for score

// ---------------- scratch (static device globals; no allocation) ----------------
__device__ float g_h[BF*NTOK*HID];       // gelu(LN(x)@w_in)  ~19.4 MB
__device__ float g_stats[2*M1];          // per-row mu, rstd
__device__ float g_gc[BF*HID];           // h[f,0,:] @ w1[256:,:]
__device__ float g_score[BF*NSP];        // sp (spatial scores only)
__device__ float g_ind[BF*TOPK*NSP];     // selection weight matrix

__device__ __forceinline__ float gelu_exact(float v){
    return 0.5f * v * (1.0f + erff(v * 0.70710678118654752440f));
}

// ---------------- K0: per-row mean / rstd ----------------
__global__ void stats_kernel(const float* __restrict__ x){
    __shared__ float xs[DIM];
    __shared__ float red[8];
    __shared__ float s_mu;
    int row = blockIdx.x;
    int t = threadIdx.x;            // 256 threads
    int lane = t & 31, wid = t >> 5;
    float2 v = *(const float2*)(x + (size_t)row*DIM + t*2);
    xs[t*2] = v.x; xs[t*2+1] = v.y;
    float s = v.x + v.y;
    #pragma unroll
    for (int o=16;o>0;o>>=1) s += __shfl_down_sync(0xFFFFFFFFu, s, o);
    if (lane==0) red[wid] = s;
    __syncthreads();
    if (t==0){
        float tot = 0.f;
        #pragma unroll
        for (int w=0;w<8;w++) tot += red[w];
        s_mu = tot * (1.0f/DIM);
    }
    __syncthreads();
    float mu = s_mu;
    float dx = xs[t*2]-mu, dy = xs[t*2+1]-mu;
    float sq = dx*dx + dy*dy;
    #pragma unroll
    for (int o=16;o>0;o>>=1) sq += __shfl_down_sync(0xFFFFFFFFu, sq, o);
    if (lane==0) red[wid] = sq;
    __syncthreads();
    if (t==0){
        float tot = 0.f;
        #pragma unroll
        for (int w=0;w<8;w++) tot += red[w];
        float var = tot * (1.0f/DIM);
        g_stats[2*row]   = mu;
        g_stats[2*row+1] = rsqrtf(var + 1e-5f);
    }
}

// ---------------- K1: h = gelu(LN(x) @ w_in)  (M1 x 512 x 256) ----------------
// BM=64, BN=64, BK=16, 256 threads, 4x4 per thread
__global__ void gemm1_kernel(const float* __restrict__ x,
                             const float* __restrict__ gamma,
                             const float* __restrict__ beta,
                             const float* __restrict__ w){
    __shared__ float As[16*64];
    __shared__ float Bs[16*64];
    int tid = threadIdx.x;
    int m0 = blockIdx.x * 64, n0 = blockIdx.y * 64;
    int tx = tid & 15, ty = tid >> 4;
    float acc[4][4];
    #pragma unroll
    for (int i=0;i<4;i++)
        #pragma unroll
        for (int j=0;j<4;j++) acc[i][j]=0.f;

    int a_row = tid >> 2;            // 0..63
    int a_k   = (tid & 3) * 4;       // 0,4,8,12
    int b_k   = tid >> 4;            // 0..15
    int b_n   = (tid & 15) * 4;
    int gm = m0 + a_row;
    bool mvalid = gm < M1;
    float mu = 0.f, rs = 0.f;
    if (mvalid){ mu = g_stats[2*gm]; rs = g_stats[2*gm+1]; }

    for (int k0=0;k0<DIM;k0+=16){
        __syncthreads();
        float4 xv = make_float4(0.f,0.f,0.f,0.f);
        if (mvalid) xv = *(const float4*)(x + (size_t)gm*DIM + k0 + a_k);
        float4 gv = *(const float4*)(gamma + k0 + a_k);
        float4 bv = *(const float4*)(beta  + k0 + a_k);
        As[(a_k+0)*64 + a_row] = (xv.x - mu)*rs*gv.x + bv.x;
        As[(a_k+1)*64 + a_row] = (xv.y - mu)*rs*gv.y + bv.y;
        As[(a_k+2)*64 + a_row] = (xv.z - mu)*rs*gv.z + bv.z;
        As[(a_k+3)*64 + a_row] = (xv.w - mu)*rs*gv.w + bv.w;
        *(float4*)(Bs + b_k*64 + b_n) = *(const float4*)(w + (size_t)(k0+b_k)*HID + n0 + b_n);
        __syncthreads();
        #pragma unroll
        for (int kk=0;kk<16;kk++){
            float4 a = *(const float4*)(As + kk*64 + ty*4);
            float4 b = *(const float4*)(Bs + kk*64 + tx*4);
            float av[4] = {a.x,a.y,a.z,a.w};
            float bv2[4] = {b.x,b.y,b.z,b.w};
            #pragma unroll
            for (int i=0;i<4;i++)
                #pragma unroll
                for (int j=0;j<4;j++) acc[i][j] += av[i]*bv2[j];
        }
    }
    #pragma unroll
    for (int i=0;i<4;i++){
        int m = m0 + ty*4 + i;
        if (m < M1){
            #pragma unroll
            for (int j=0;j<4;j++){
                g_h[(size_t)m*HID + n0 + tx*4 + j] = gelu_exact(acc[i][j]);
            }
        }
    }
}

// ---------------- K2: gcontrib[f,j] = sum_k h[f,0,k] * w1[256+k, j] ----------------
__global__ void gc_kernel(const float* __restrict__ w1){
    __shared__ float h0[HID];
    int f = blockIdx.x, j = threadIdx.x;
    h0[j] = g_h[(size_t)(f*NTOK)*HID + j];
    __syncthreads();
    float acc = 0.f;
    #pragma unroll 4
    for (int k=0;k<HID;k++)
        acc += h0[k] * w1[(size_t)(HID+k)*HID + j];
    g_gc[f*HID + j] = acc;
}

// ---------------- K3: score = tanh(gelu(h@w1_top + gc) @ w2)  (spatial tokens only) ----------------
// 32 rows per block, 256 threads (thread = hidden column j)
__global__ void score_kernel(const float* __restrict__ w1,
                             const float* __restrict__ w2){
    __shared__ float hs[32*HID];
    __shared__ float sred[32*8];
    int j = threadIdx.x;
    int lane = j & 31, wid = j >> 5;
    int row0 = blockIdx.x * 32;
    for (int r=0;r<32;r++){
        int row = row0 + r;
        int f = row / NSP;
        int i = row - f*NSP;
        hs[r*HID + j] = g_h[(size_t)(f*NTOK + 1 + i)*HID + j];
    }
    __syncthreads();
    float acc[32];
    #pragma unroll
    for (int r=0;r<32;r++) acc[r]=0.f;
    #pragma unroll 2
    for (int k=0;k<HID;k++){
        float wv = w1[(size_t)k*HID + j];
        #pragma unroll
        for (int r=0;r<32;r++) acc[r] += hs[r*HID + k] * wv;
    }
    float w2v = w2[j];
    #pragma unroll
    for (int r=0;r<32;r++){
        int row = row0 + r;
        int f = row / NSP;
        float u = acc[r] + g_gc[f*HID + j];
        float val = gelu_exact(u) * w2v;
        #pragma unroll
        for (int o=16;o>0;o>>=1) val += __shfl_down_sync(0xFFFFFFFFu, val, o);
        if (lane==0) sred[r*8 + wid] = val;
    }
    __syncthreads();
    if (j < 32){
        float s = 0.f;
        #pragma unroll
        for (int w=0;w<8;w++) s += sred[j*8 + w];
        g_score[row0 + j] = tanhf(s);
    }
}

// ---------------- K4a: zero ind ----------------
__global__ void zero_ind_kernel(){
    int i = blockIdx.x*256 + threadIdx.x;
    if (i < BF*TOPK*NSP) g_ind[i] = 0.f;
}

// ---------------- K4: top-49 selection, accumulate ind ----------------
// grid = BF*32 blocks; 256 threads = 8 warps; one warp per sample
__global__ void select_kernel(const float* __restrict__ noise){
    __shared__ float sps[NSP];
    __shared__ unsigned long long keys[8][200];
    int bf = blockIdx.x >> 5;
    int sg = blockIdx.x & 31;
    int wid = threadIdx.x >> 5, lane = threadIdx.x & 31;
    int s = sg*8 + wid;
    if (threadIdx.x < NSP) sps[threadIdx.x] = g_score[bf*NSP + threadIdx.x];
    __syncthreads();
    const float* np = noise + (size_t)(bf*NS + s)*NSP;

    unsigned long long K[7];
    int cnt[7];
    #pragma unroll
    for (int c=0;c<7;c++){
        int l = c*32 + lane;
        unsigned long long kk = 0ull;
        if (l < NSP){
            float p = sps[l] + SIGMA * np[l];
            unsigned u = __float_as_uint(p);
            u ^= (u & 0x80000000u) ? 0xFFFFFFFFu : 0x80000000u;   // monotone key
            kk = ((unsigned long long)u << 8) | (unsigned)(255 - l); // tie: lower l -> bigger key
            keys[wid][l] = kk;
        }
        K[c] = kk;
        cnt[c] = (l < NSP) ? 0 : 100000;
    }
    __syncwarp();
    for (int lp=0; lp<NSP; lp++){
        unsigned long long kv = keys[wid][lp];
        #pragma unroll
        for (int c=0;c<7;c++) cnt[c] += (kv > K[c]) ? 1 : 0;
    }
    // selected = rank < TOPK; position k = prefix count of selected with smaller l
    int pre = 0;
    #pragma unroll
    for (int c=0;c<7;c++){
        bool sel = cnt[c] < TOPK;
        unsigned bal = __ballot_sync(0xFFFFFFFFu, sel);
        int l = c*32 + lane;
        if (sel && l < NSP){
            int k = pre + __popc(bal & ((1u<<lane)-1u));
            atomicAdd(&g_ind[((size_t)bf*TOPK + k)*NSP + l], 1.0f/NS);
        }
        pre += __popc(bal);
    }
}

// ---------------- K5: out = [cls ; ind @ spat] ----------------
// grid (BF, 2), 256 threads (thread = one d within a 256 chunk)
__global__ void output_kernel(const float* __restrict__ x, float* __restrict__ out){
    __shared__ float inds[TOPK*NSP];
    int bf = blockIdx.x;
    int d0 = blockIdx.y * 256;
    int t = threadIdx.x;
    for (int i=t; i<TOPK*NSP; i+=256) inds[i] = g_ind[(size_t)bf*TOPK*NSP + i];
    __syncthreads();
    float acc[TOPK];
    #pragma unroll
    for (int k=0;k<TOPK;k++) acc[k]=0.f;
    const float* xb = x + (size_t)(bf*NTOK)*DIM + d0 + t;
    for (int l=0;l<NSP;l++){
        float xv = xb[(size_t)(l+1)*DIM];
        #pragma unroll
        for (int k=0;k<TOPK;k++) acc[k] += inds[k*NSP + l] * xv;
    }
    float* ob = out + (size_t)(bf*(1+TOPK))*DIM + d0 + t;
    ob[0] = xb[0]; // cls passthrough
    #pragma unroll
    for (int k=0;k<TOPK;k++) ob[(size_t)(k+1)*DIM] = acc[k];
}

// ---------------- launcher ----------------
extern "C" void kernel_launch(void* const* d_in, const int* in_sizes, int n_in,
                              void* d_out, int out_size){
    const float* x     = (const float*)d_in[0];
    const float* noise = (const float*)d_in[1];
    const float* gamma = (const float*)d_in[2];
    const float* beta  = (const float*)d_in[3];
    const float* w_in  = (const float*)d_in[4];
    const float* w1    = (const float*)d_in[5];
    const float* w2    = (const float*)d_in[6];
    float* out = (float*)d_out;

    stats_kernel<<<M1, 256>>>(x);
    dim3 g1((M1 + 63)/64, HID/64);
    gemm1_kernel<<<g1, 256>>>(x, gamma, beta, w_in);
    gc_kernel<<<BF, 256>>>(w1);
    score_kernel<<<M3/32, 256>>>(w1, w2);
    zero_ind_kernel<<<(BF*TOPK*NSP + 255)/256, 256>>>();
    select_kernel<<<BF*32, 256>>>(noise);
    dim3 g5(BF, 2);
    output_kernel<<<g5, 256>>>(x, out);
}

// round 2
// speedup vs baseline: 1.2455x; 1.2455x over previous
#include <cuda_runtime.h>
#include <cuda_bf16.h>
#include <math.h>

// Problem constants
#define BF      96          // B * MAX_FRAMES
#define NTOK    197
#define NSP     196
#define DIM     512
#define HID     256
#define TOPK    49
#define NS      256
#define SIGMA   0.05f
#define M1      (BF*NTOK)   // 18912 rows for GEMM1
#define M3      (BF*NSP)    // 18816 rows for score (== 294*64 exactly)

typedef unsigned long long u64;

// ---------------- scratch ----------------
__device__ float g_h[BF*NTOK*HID];       // gelu(LN(x)@w_in)
__device__ float g_stats[2*M1];          // per-row mu, rstd
__device__ float g_gc[BF*HID];           // h[f,0,:] @ w1[256:,:]
__device__ float g_score[BF*NSP];        // spatial scores
__device__ float g_ind[BF*TOPK*NSP];     // selection weight matrix

__device__ __forceinline__ float gelu_exact(float v){
    return 0.5f * v * (1.0f + erff(v * 0.70710678118654752440f));
}

// ---- packed fp32x2 (Blackwell) : bitwise identical to 2x scalar fmaf ----
__device__ __forceinline__ void ffma2(u64 &d, u64 a, u64 b){
    asm("fma.rn.f32x2 %0, %1, %2, %0;" : "+l"(d) : "l"(a), "l"(b));
}
__device__ __forceinline__ u64 pk2(float lo, float hi){
    u64 r; asm("mov.b64 %0, {%1, %2};" : "=l"(r) : "f"(lo), "f"(hi)); return r;
}
__device__ __forceinline__ void upk2(u64 v, float &lo, float &hi){
    asm("mov.b64 {%0, %1}, %2;" : "=f"(lo), "=f"(hi) : "l"(v));
}

// ---------------- K0: per-row mean / rstd ----------------
__global__ void stats_kernel(const float* __restrict__ x){
    __shared__ float xs[DIM];
    __shared__ float red[8];
    __shared__ float s_mu;
    int row = blockIdx.x;
    int t = threadIdx.x;
    int lane = t & 31, wid = t >> 5;
    float2 v = *(const float2*)(x + (size_t)row*DIM + t*2);
    xs[t*2] = v.x; xs[t*2+1] = v.y;
    float s = v.x + v.y;
    #pragma unroll
    for (int o=16;o>0;o>>=1) s += __shfl_down_sync(0xFFFFFFFFu, s, o);
    if (lane==0) red[wid] = s;
    __syncthreads();
    if (t==0){
        float tot = 0.f;
        #pragma unroll
        for (int w=0;w<8;w++) tot += red[w];
        s_mu = tot * (1.0f/DIM);
    }
    __syncthreads();
    float mu = s_mu;
    float dx = xs[t*2]-mu, dy = xs[t*2+1]-mu;
    float sq = dx*dx + dy*dy;
    #pragma unroll
    for (int o=16;o>0;o>>=1) sq += __shfl_down_sync(0xFFFFFFFFu, sq, o);
    if (lane==0) red[wid] = sq;
    __syncthreads();
    if (t==0){
        float tot = 0.f;
        #pragma unroll
        for (int w=0;w<8;w++) tot += red[w];
        float var = tot * (1.0f/DIM);
        g_stats[2*row]   = mu;
        g_stats[2*row+1] = rsqrtf(var + 1e-5f);
    }
}

// ---------------- K1: h = gelu(LN(x) @ w_in)  (M1 x 512 x 256) ----------------
// BM=128, BN=128, BK=8, 256 threads. Per thread: 8 rows (4 packed pairs) x 8 cols.
// B duplicated in smem so each col's (b,b) pair is one conflict-free LDS.64.
__global__ __launch_bounds__(256,2) void gemm1_kernel(const float* __restrict__ x,
                             const float* __restrict__ gamma,
                             const float* __restrict__ beta,
                             const float* __restrict__ w){
    __shared__ float As[2][8][128];   // 8 KB
    __shared__ float Bs[2][8][256];   // 16 KB (duplicated cols)
    int tid = threadIdx.x;
    int m0 = blockIdx.x * 128, n0 = blockIdx.y * 128;
    int tx = tid & 15;        // col group: cols j = tx + 16*jj
    int ty = tid >> 4;        // row group: rows ty*8 .. +8

    // A loader: one row per thread, 8 k's via 2 float4... (BK=8 -> 1 float4 pair split)
    int arow = tid & 127;
    int ak   = (tid >> 7) * 4;       // 0 or 4
    int gm = m0 + arow;
    bool av = gm < M1;
    float mu = 0.f, rs = 0.f;
    if (av){ mu = g_stats[2*gm]; rs = g_stats[2*gm+1]; }
    const float* xrow = x + (size_t)gm*DIM;
    // B loader
    int bk = tid >> 5;               // 0..7
    int bn = (tid & 31) * 4;         // 0..124

    u64 acc[4][8];
    #pragma unroll
    for (int i=0;i<4;i++)
        #pragma unroll
        for (int j=0;j<8;j++) acc[i][j] = 0ull;

    float4 va, wb;
    // ldg tile 0
    {
        int k0 = 0;
        if (av){
            float4 xa = *(const float4*)(xrow + k0 + ak);
            float4 ga = *(const float4*)(gamma + k0 + ak);
            float4 ba = *(const float4*)(beta  + k0 + ak);
            va.x = (xa.x-mu)*rs*ga.x + ba.x;
            va.y = (xa.y-mu)*rs*ga.y + ba.y;
            va.z = (xa.z-mu)*rs*ga.z + ba.z;
            va.w = (xa.w-mu)*rs*ga.w + ba.w;
        } else va = make_float4(0.f,0.f,0.f,0.f);
        wb = *(const float4*)(w + (size_t)(k0+bk)*HID + n0 + bn);
    }
    // sts tile 0 -> buf 0
    As[0][ak+0][arow] = va.x;
    As[0][ak+1][arow] = va.y;
    As[0][ak+2][arow] = va.z;
    As[0][ak+3][arow] = va.w;
    *(float4*)&Bs[0][bk][2*bn]   = make_float4(wb.x,wb.x,wb.y,wb.y);
    *(float4*)&Bs[0][bk][2*bn+4] = make_float4(wb.z,wb.z,wb.w,wb.w);
    __syncthreads();

    int buf = 0;
    const int T = DIM/8;   // 64
    for (int t=0; t<T; t++){
        if (t+1 < T){
            int k0 = (t+1)*8;
            if (av){
                float4 xa = *(const float4*)(xrow + k0 + ak);
                float4 ga = *(const float4*)(gamma + k0 + ak);
                float4 ba = *(const float4*)(beta  + k0 + ak);
                va.x = (xa.x-mu)*rs*ga.x + ba.x;
                va.y = (xa.y-mu)*rs*ga.y + ba.y;
                va.z = (xa.z-mu)*rs*ga.z + ba.z;
                va.w = (xa.w-mu)*rs*ga.w + ba.w;
            } else va = make_float4(0.f,0.f,0.f,0.f);
            wb = *(const float4*)(w + (size_t)(k0+bk)*HID + n0 + bn);
        }
        #pragma unroll
        for (int kk=0;kk<8;kk++){
            const u64* ap = (const u64*)&As[buf][kk][ty*8];
            u64 a0 = ap[0], a1 = ap[1], a2 = ap[2], a3 = ap[3];
            #pragma unroll
            for (int jj=0;jj<8;jj++){
                u64 b2 = *(const u64*)&Bs[buf][kk][2*(tx + 16*jj)];
                ffma2(acc[0][jj], a0, b2);
                ffma2(acc[1][jj], a1, b2);
                ffma2(acc[2][jj], a2, b2);
                ffma2(acc[3][jj], a3, b2);
            }
        }
        if (t+1 < T){
            int nb = buf ^ 1;
            As[nb][ak+0][arow] = va.x;
            As[nb][ak+1][arow] = va.y;
            As[nb][ak+2][arow] = va.z;
            As[nb][ak+3][arow] = va.w;
            *(float4*)&Bs[nb][bk][2*bn]   = make_float4(wb.x,wb.x,wb.y,wb.y);
            *(float4*)&Bs[nb][bk][2*bn+4] = make_float4(wb.z,wb.z,wb.w,wb.w);
            __syncthreads();
            buf = nb;
        }
    }
    // epilogue: gelu + store
    int r0 = m0 + ty*8;
    #pragma unroll
    for (int rp=0;rp<4;rp++){
        int rlo = r0 + 2*rp, rhi = rlo + 1;
        bool slo = rlo < M1, shi = rhi < M1;
        #pragma unroll
        for (int jj=0;jj<8;jj++){
            float lo, hi;
            upk2(acc[rp][jj], lo, hi);
            int col = n0 + tx + 16*jj;
            if (slo) g_h[(size_t)rlo*HID + col] = gelu_exact(lo);
            if (shi) g_h[(size_t)rhi*HID + col] = gelu_exact(hi);
        }
    }
}

// ---------------- K2: gcontrib[f,j] = sum_k h[f,0,k] * w1[256+k, j] ----------------
__global__ void gc_kernel(const float* __restrict__ w1){
    __shared__ float h0[HID];
    int f = blockIdx.x, j = threadIdx.x;
    h0[j] = g_h[(size_t)(f*NTOK)*HID + j];
    __syncthreads();
    float acc = 0.f;
    #pragma unroll 4
    for (int k=0;k<HID;k++)
        acc += h0[k] * w1[(size_t)(HID+k)*HID + j];
    g_gc[f*HID + j] = acc;
}

// ---------------- K3: score = tanh(gelu(h@w1_top + gc) @ w2) ----------------
// BM=64 rows, BN=256 (full width, reduced in-block), BK=8, 256 threads.
// Warp wid handles rows wid*8..+8 (4 packed pairs) over all 256 cols (lane+32*jj).
__global__ __launch_bounds__(256,2) void score_kernel(const float* __restrict__ w1,
                             const float* __restrict__ w2){
    __shared__ float As[2][8][64];    // 4 KB
    __shared__ float Bs[2][8][512];   // 32 KB (duplicated cols)
    int tid = threadIdx.x;
    int lane = tid & 31, wid = tid >> 5;
    int m0 = blockIdx.x * 64;

    // A loader: row = tid&63, 2 k's
    int arow = tid & 63;
    int akb  = (tid >> 6) * 2;   // 0,2,4,6
    int m = m0 + arow;
    int f_ld = m / NSP;
    int i_ld = m - f_ld*NSP;
    const float* hrow = g_h + (size_t)(f_ld*NTOK + 1 + i_ld)*HID;
    // B loader
    int bk = tid >> 5;            // 0..7
    int bn = (tid & 31) * 8;      // 0..248

    u64 acc[4][8];
    #pragma unroll
    for (int i=0;i<4;i++)
        #pragma unroll
        for (int j=0;j<8;j++) acc[i][j] = 0ull;

    float2 va; float4 wb0, wb1;
    {
        va = *(const float2*)(hrow + akb);
        wb0 = *(const float4*)(w1 + (size_t)bk*HID + bn);
        wb1 = *(const float4*)(w1 + (size_t)bk*HID + bn + 4);
    }
    As[0][akb][arow]   = va.x;
    As[0][akb+1][arow] = va.y;
    *(float4*)&Bs[0][bk][2*bn]    = make_float4(wb0.x,wb0.x,wb0.y,wb0.y);
    *(float4*)&Bs[0][bk][2*bn+4]  = make_float4(wb0.z,wb0.z,wb0.w,wb0.w);
    *(float4*)&Bs[0][bk][2*bn+8]  = make_float4(wb1.x,wb1.x,wb1.y,wb1.y);
    *(float4*)&Bs[0][bk][2*bn+12] = make_float4(wb1.z,wb1.z,wb1.w,wb1.w);
    __syncthreads();

    int buf = 0;
    const int T = HID/8;  // 32
    for (int t=0;t<T;t++){
        if (t+1 < T){
            int k0 = (t+1)*8;
            va = *(const float2*)(hrow + k0 + akb);
            wb0 = *(const float4*)(w1 + (size_t)(k0+bk)*HID + bn);
            wb1 = *(const float4*)(w1 + (size_t)(k0+bk)*HID + bn + 4);
        }
        #pragma unroll
        for (int kk=0;kk<8;kk++){
            const u64* ap = (const u64*)&As[buf][kk][wid*8];
            u64 a0 = ap[0], a1 = ap[1], a2 = ap[2], a3 = ap[3];
            #pragma unroll
            for (int jj=0;jj<8;jj++){
                u64 b2 = *(const u64*)&Bs[buf][kk][2*(lane + 32*jj)];
                ffma2(acc[0][jj], a0, b2);
                ffma2(acc[1][jj], a1, b2);
                ffma2(acc[2][jj], a2, b2);
                ffma2(acc[3][jj], a3, b2);
            }
        }
        if (t+1 < T){
            int nb = buf ^ 1;
            As[nb][akb][arow]   = va.x;
            As[nb][akb+1][arow] = va.y;
            *(float4*)&Bs[nb][bk][2*bn]    = make_float4(wb0.x,wb0.x,wb0.y,wb0.y);
            *(float4*)&Bs[nb][bk][2*bn+4]  = make_float4(wb0.z,wb0.z,wb0.w,wb0.w);
            *(float4*)&Bs[nb][bk][2*bn+8]  = make_float4(wb1.x,wb1.x,wb1.y,wb1.y);
            *(float4*)&Bs[nb][bk][2*bn+12] = make_float4(wb1.z,wb1.z,wb1.w,wb1.w);
            __syncthreads();
            buf = nb;
        }
    }
    // epilogue: u + gc -> gelu -> *w2 -> row reduce
    int rbase = m0 + wid*8;
    int fr[8];
    #pragma unroll
    for (int rr=0;rr<8;rr++) fr[rr] = (rbase + rr) / NSP;
    float s[8];
    #pragma unroll
    for (int rr=0;rr<8;rr++) s[rr] = 0.f;
    #pragma unroll
    for (int jj=0;jj<8;jj++){
        int j = lane + 32*jj;
        float w2v = w2[j];
        #pragma unroll
        for (int rp=0;rp<4;rp++){
            float lo, hi;
            upk2(acc[rp][jj], lo, hi);
            float glo = g_gc[fr[2*rp]*HID + j];
            float ghi = g_gc[fr[2*rp+1]*HID + j];
            s[2*rp]   += gelu_exact(lo + glo) * w2v;
            s[2*rp+1] += gelu_exact(hi + ghi) * w2v;
        }
    }
    #pragma unroll
    for (int rr=0;rr<8;rr++){
        float v = s[rr];
        #pragma unroll
        for (int o=16;o>0;o>>=1) v += __shfl_xor_sync(0xFFFFFFFFu, v, o);
        s[rr] = v;
    }
    if (lane == 0){
        #pragma unroll
        for (int rr=0;rr<8;rr++)
            g_score[rbase + rr] = tanhf(s[rr]);
    }
}

// ---------------- K4a: zero ind ----------------
__global__ void zero_ind_kernel(){
    int i = blockIdx.x*256 + threadIdx.x;
    if (i < BF*TOPK*NSP) g_ind[i] = 0.f;
}

// ---------------- K4: top-49 selection via exact 40-bit binary search ----------------
// grid = BF*32 blocks; 8 warps; one warp per sample. Keys are unique (index in
// low 8 bits), so the 49th-largest key is found bitwise and sel = key >= K49.
__global__ void select_kernel(const float* __restrict__ noise){
    __shared__ float sps[NSP];
    int bf = blockIdx.x >> 5;
    int sg = blockIdx.x & 31;
    int wid = threadIdx.x >> 5, lane = threadIdx.x & 31;
    int s = sg*8 + wid;
    if (threadIdx.x < NSP) sps[threadIdx.x] = g_score[bf*NSP + threadIdx.x];
    __syncthreads();
    const float* np = noise + (size_t)(bf*NS + s)*NSP;

    u64 K[7];
    #pragma unroll
    for (int c=0;c<7;c++){
        int l = c*32 + lane;
        u64 kk = 0ull;
        if (l < NSP){
            float p = sps[l] + SIGMA * np[l];
            unsigned u = __float_as_uint(p);
            u ^= (u & 0x80000000u) ? 0xFFFFFFFFu : 0x80000000u;     // monotone key
            kk = ((u64)u << 8) | (unsigned)(255 - l);               // tie: lower l wins
        }
        K[c] = kk;
    }
    // binary search the 49th-largest key (keys distinct, invalid = 0 never selected)
    u64 pref = 0ull;
    #pragma unroll 1
    for (int b=39;b>=0;b--){
        u64 cand = pref | (1ull << b);
        unsigned cnt = 0;
        #pragma unroll
        for (int c=0;c<7;c++) cnt += (K[c] >= cand) ? 1u : 0u;
        cnt = __reduce_add_sync(0xFFFFFFFFu, cnt);
        if (cnt >= TOPK) pref = cand;
    }
    // selected = key >= pref (exactly 49); position = prefix count in l order
    int pre = 0;
    #pragma unroll
    for (int c=0;c<7;c++){
        bool sel = (K[c] >= pref);
        unsigned bal = __ballot_sync(0xFFFFFFFFu, sel);
        int l = c*32 + lane;
        if (sel){
            int k = pre + __popc(bal & ((1u<<lane)-1u));
            atomicAdd(&g_ind[((size_t)bf*TOPK + k)*NSP + l], 1.0f/NS);
        }
        pre += __popc(bal);
    }
}

// ---------------- K5: out = [cls ; ind @ spat]  (f32x2 over k-pairs) ----------------
// grid (BF, 4), 128 threads; ind transposed into smem padded to 50 so k-pairs
// are contiguous 8-byte words.
__global__ void output_kernel(const float* __restrict__ x, float* __restrict__ out){
    __shared__ float indsT[NSP][TOPK+1];   // 196*50*4 = 39.2 KB
    int bf = blockIdx.x;
    int d  = blockIdx.y * 128 + threadIdx.x;
    int t  = threadIdx.x;
    #pragma unroll 1
    for (int k=0;k<TOPK;k++)
        for (int l=t; l<NSP; l+=128)
            indsT[l][k] = g_ind[((size_t)bf*TOPK + k)*NSP + l];
    for (int l=t; l<NSP; l+=128) indsT[l][TOPK] = 0.f;
    __syncthreads();

    u64 acc[25];
    #pragma unroll
    for (int kp=0;kp<25;kp++) acc[kp] = 0ull;
    const float* xb = x + (size_t)(bf*NTOK)*DIM + d;
    #pragma unroll 1
    for (int l=0;l<NSP;l++){
        float xv = xb[(size_t)(l+1)*DIM];
        u64 x2 = pk2(xv, xv);
        const u64* row = (const u64*)indsT[l];
        #pragma unroll
        for (int kp=0;kp<25;kp++) ffma2(acc[kp], x2, row[kp]);
    }
    float* ob = out + (size_t)(bf*(1+TOPK))*DIM + d;
    ob[0] = xb[0];   // cls passthrough
    #pragma unroll
    for (int kp=0;kp<25;kp++){
        float lo, hi;
        upk2(acc[kp], lo, hi);
        ob[(size_t)(2*kp+1)*DIM] = lo;
        if (kp < 24) ob[(size_t)(2*kp+2)*DIM] = hi;
    }
}

// ---------------- launcher ----------------
extern "C" void kernel_launch(void* const* d_in, const int* in_sizes, int n_in,
                              void* d_out, int out_size){
    const float* x     = (const float*)d_in[0];
    const float* noise = (const float*)d_in[1];
    const float* gamma = (const float*)d_in[2];
    const float* beta  = (const float*)d_in[3];
    const float* w_in  = (const float*)d_in[4];
    const float* w1    = (const float*)d_in[5];
    const float* w2    = (const float*)d_in[6];
    float* out = (float*)d_out;

    stats_kernel<<<M1, 256>>>(x);
    dim3 g1((M1 + 127)/128, HID/128);
    gemm1_kernel<<<g1, 256>>>(x, gamma, beta, w_in);
    gc_kernel<<<BF, 256>>>(w1);
    score_kernel<<<M3/64, 256>>>(w1, w2);
    zero_ind_kernel<<<(BF*TOPK*NSP + 255)/256, 256>>>();
    select_kernel<<<BF*32, 256>>>(noise);
    dim3 g5(BF, 4);
    output_kernel<<<g5, 128>>>(x, out);
}

// round 3
// speedup vs baseline: 1.3540x; 1.0871x over previous
#include <cuda_runtime.h>
#include <cuda_bf16.h>
#include <math.h>

// Problem constants
#define BF      96          // B * MAX_FRAMES
#define NTOK    197
#define NSP     196
#define DIM     512
#define HID     256
#define TOPK    49
#define NS      256
#define SIGMA   0.05f
#define M1      (BF*NTOK)   // 18912 rows for GEMM1
#define M3      (BF*NSP)    // 18816 rows for score (== 147*128 exactly)

typedef unsigned long long u64;

// ---------------- scratch ----------------
__device__ float g_h[BF*NTOK*HID];       // gelu(LN(x)@w_in)
__device__ float g_stats[2*M1];          // per-row mu, rstd
__device__ float g_gc[BF*HID];           // h[f,0,:] @ w1[256:,:]
__device__ float g_score[BF*NSP];        // spatial scores
__device__ float g_ind[BF*TOPK*NSP];     // selection weight matrix

__device__ __forceinline__ float gelu_exact(float v){
    return 0.5f * v * (1.0f + erff(v * 0.70710678118654752440f));
}

// ---- packed fp32x2 (Blackwell) : bitwise identical to 2x scalar fmaf ----
__device__ __forceinline__ void ffma2(u64 &d, u64 a, u64 b){
    asm("fma.rn.f32x2 %0, %1, %2, %0;" : "+l"(d) : "l"(a), "l"(b));
}
__device__ __forceinline__ u64 pk2(float lo, float hi){
    u64 r; asm("mov.b64 %0, {%1, %2};" : "=l"(r) : "f"(lo), "f"(hi)); return r;
}
__device__ __forceinline__ void upk2(u64 v, float &lo, float &hi){
    asm("mov.b64 {%0, %1}, %2;" : "=f"(lo), "=f"(hi) : "l"(v));
}

// ---------------- K0: per-row mean / rstd (1 warp per row) ----------------
__global__ void stats_kernel(const float* __restrict__ x){
    int wid = threadIdx.x >> 5, lane = threadIdx.x & 31;
    int row = blockIdx.x*8 + wid;
    if (row >= M1) return;
    const float* xr = x + (size_t)row*DIM;
    float4 v[4];
    float s = 0.f;
    #pragma unroll
    for (int i=0;i<4;i++){
        v[i] = *(const float4*)(xr + i*128 + lane*4);
        s += v[i].x + v[i].y + v[i].z + v[i].w;
    }
    #pragma unroll
    for (int o=16;o>0;o>>=1) s += __shfl_xor_sync(0xFFFFFFFFu, s, o);
    float mu = s * (1.0f/DIM);
    float sq = 0.f;
    #pragma unroll
    for (int i=0;i<4;i++){
        float a=v[i].x-mu, b=v[i].y-mu, c=v[i].z-mu, d=v[i].w-mu;
        sq += a*a + b*b + c*c + d*d;
    }
    #pragma unroll
    for (int o=16;o>0;o>>=1) sq += __shfl_xor_sync(0xFFFFFFFFu, sq, o);
    if (lane==0){
        g_stats[2*row]   = mu;
        g_stats[2*row+1] = rsqrtf(sq * (1.0f/DIM) + 1e-5f);
    }
}

// ---------------- K1: h = gelu(LN(x) @ w_in)  (M1 x 512 x 256) ----------------
// BM=128, BN=256 (full), BK=8, 512 threads (16 warps). Warp = 8 rows x 256 cols.
// Per thread: 4 row-pairs x 8 cols. B loaded scalar (LDS.32) + reg dup.
__global__ __launch_bounds__(512,1) void gemm1_kernel(const float* __restrict__ x,
                             const float* __restrict__ gamma,
                             const float* __restrict__ beta,
                             const float* __restrict__ w){
    __shared__ float As[2][8][128];   // 4 KB/buf
    __shared__ float Bs[2][8][256];   // 8 KB/buf
    int tid = threadIdx.x;
    int lane = tid & 31, wid = tid >> 5;
    int m0 = blockIdx.x * 128;

    // A loader: row = tid&127, two k's at (tid>>7)*2
    int arow = tid & 127;
    int ak   = (tid >> 7) * 2;           // 0,2,4,6
    int gm = m0 + arow;
    bool av = gm < M1;
    float mu = 0.f, rs = 0.f;
    if (av){ mu = g_stats[2*gm]; rs = g_stats[2*gm+1]; }
    const float* xrow = x + (size_t)gm*DIM;
    // B loader: k = tid>>6 (0..7), n = (tid&63)*4
    int bk = tid >> 6;
    int bn = (tid & 63) * 4;

    u64 acc[4][8];
    #pragma unroll
    for (int i=0;i<4;i++)
        #pragma unroll
        for (int j=0;j<8;j++) acc[i][j] = 0ull;

    float2 va; float4 wb;
    {
        if (av){
            float2 xa = *(const float2*)(xrow + ak);
            float2 ga = *(const float2*)(gamma + ak);
            float2 ba = *(const float2*)(beta  + ak);
            va.x = (xa.x-mu)*rs*ga.x + ba.x;
            va.y = (xa.y-mu)*rs*ga.y + ba.y;
        } else va = make_float2(0.f,0.f);
        wb = *(const float4*)(w + (size_t)bk*HID + bn);
    }
    As[0][ak][arow]   = va.x;
    As[0][ak+1][arow] = va.y;
    *(float4*)&Bs[0][bk][bn] = wb;
    __syncthreads();

    int buf = 0;
    const int T = DIM/8;   // 64
    for (int t=0; t<T; t++){
        if (t+1 < T){
            int k0 = (t+1)*8;
            if (av){
                float2 xa = *(const float2*)(xrow + k0 + ak);
                float2 ga = *(const float2*)(gamma + k0 + ak);
                float2 ba = *(const float2*)(beta  + k0 + ak);
                va.x = (xa.x-mu)*rs*ga.x + ba.x;
                va.y = (xa.y-mu)*rs*ga.y + ba.y;
            } else va = make_float2(0.f,0.f);
            wb = *(const float4*)(w + (size_t)(k0+bk)*HID + bn);
        }
        #pragma unroll
        for (int kk=0;kk<8;kk++){
            const u64* ap = (const u64*)&As[buf][kk][wid*8];
            u64 a0 = ap[0], a1 = ap[1], a2 = ap[2], a3 = ap[3];
            #pragma unroll
            for (int jj=0;jj<8;jj++){
                float bv = Bs[buf][kk][lane + 32*jj];
                u64 b2 = pk2(bv, bv);
                ffma2(acc[0][jj], a0, b2);
                ffma2(acc[1][jj], a1, b2);
                ffma2(acc[2][jj], a2, b2);
                ffma2(acc[3][jj], a3, b2);
            }
        }
        if (t+1 < T){
            int nb = buf ^ 1;
            As[nb][ak][arow]   = va.x;
            As[nb][ak+1][arow] = va.y;
            *(float4*)&Bs[nb][bk][bn] = wb;
            __syncthreads();
            buf = nb;
        }
    }
    // epilogue: gelu + store
    int r0 = m0 + wid*8;
    #pragma unroll
    for (int rp=0;rp<4;rp++){
        int rlo = r0 + 2*rp, rhi = rlo + 1;
        bool slo = rlo < M1, shi = rhi < M1;
        #pragma unroll
        for (int jj=0;jj<8;jj++){
            float lo, hi;
            upk2(acc[rp][jj], lo, hi);
            int col = lane + 32*jj;
            if (slo) g_h[(size_t)rlo*HID + col] = gelu_exact(lo);
            if (shi) g_h[(size_t)rhi*HID + col] = gelu_exact(hi);
        }
    }
}

// ---------------- K2: gcontrib[f,j] = sum_k h[f,0,k] * w1[256+k, j] ----------------
__global__ void gc_kernel(const float* __restrict__ w1){
    __shared__ float h0[HID];
    int f = blockIdx.x, j = threadIdx.x;
    h0[j] = g_h[(size_t)(f*NTOK)*HID + j];
    __syncthreads();
    float acc = 0.f;
    #pragma unroll 4
    for (int k=0;k<HID;k++)
        acc += h0[k] * w1[(size_t)(HID+k)*HID + j];
    g_gc[f*HID + j] = acc;
}

// ---------------- K3: score = tanh(gelu(h@w1_top + gc) @ w2) ----------------
// BM=128, BN=256 (full, reduced in epilogue), BK=8, 512 threads (16 warps).
__global__ __launch_bounds__(512,1) void score_kernel(const float* __restrict__ w1,
                             const float* __restrict__ w2){
    __shared__ float As[2][8][128];
    __shared__ float Bs[2][8][256];
    int tid = threadIdx.x;
    int lane = tid & 31, wid = tid >> 5;
    int m0 = blockIdx.x * 128;

    // A loader
    int arow = tid & 127;
    int ak   = (tid >> 7) * 2;
    int m = m0 + arow;
    int f_ld = m / NSP;
    int i_ld = m - f_ld*NSP;
    const float* hrow = g_h + (size_t)(f_ld*NTOK + 1 + i_ld)*HID;
    // B loader
    int bk = tid >> 6;
    int bn = (tid & 63) * 4;

    u64 acc[4][8];
    #pragma unroll
    for (int i=0;i<4;i++)
        #pragma unroll
        for (int j=0;j<8;j++) acc[i][j] = 0ull;

    float2 va; float4 wb;
    {
        va = *(const float2*)(hrow + ak);
        wb = *(const float4*)(w1 + (size_t)bk*HID + bn);
    }
    As[0][ak][arow]   = va.x;
    As[0][ak+1][arow] = va.y;
    *(float4*)&Bs[0][bk][bn] = wb;
    __syncthreads();

    int buf = 0;
    const int T = HID/8;  // 32
    for (int t=0;t<T;t++){
        if (t+1 < T){
            int k0 = (t+1)*8;
            va = *(const float2*)(hrow + k0 + ak);
            wb = *(const float4*)(w1 + (size_t)(k0+bk)*HID + bn);
        }
        #pragma unroll
        for (int kk=0;kk<8;kk++){
            const u64* ap = (const u64*)&As[buf][kk][wid*8];
            u64 a0 = ap[0], a1 = ap[1], a2 = ap[2], a3 = ap[3];
            #pragma unroll
            for (int jj=0;jj<8;jj++){
                float bv = Bs[buf][kk][lane + 32*jj];
                u64 b2 = pk2(bv, bv);
                ffma2(acc[0][jj], a0, b2);
                ffma2(acc[1][jj], a1, b2);
                ffma2(acc[2][jj], a2, b2);
                ffma2(acc[3][jj], a3, b2);
            }
        }
        if (t+1 < T){
            int nb = buf ^ 1;
            As[nb][ak][arow]   = va.x;
            As[nb][ak+1][arow] = va.y;
            *(float4*)&Bs[nb][bk][bn] = wb;
            __syncthreads();
            buf = nb;
        }
    }
    // epilogue: u + gc -> gelu -> *w2 -> row reduce (rows wid*8..+8, cols lane+32jj)
    int rbase = m0 + wid*8;
    int fr[8];
    #pragma unroll
    for (int rr=0;rr<8;rr++) fr[rr] = (rbase + rr) / NSP;
    float s[8];
    #pragma unroll
    for (int rr=0;rr<8;rr++) s[rr] = 0.f;
    #pragma unroll
    for (int jj=0;jj<8;jj++){
        int j = lane + 32*jj;
        float w2v = w2[j];
        #pragma unroll
        for (int rp=0;rp<4;rp++){
            float lo, hi;
            upk2(acc[rp][jj], lo, hi);
            float glo = g_gc[fr[2*rp]*HID + j];
            float ghi = g_gc[fr[2*rp+1]*HID + j];
            s[2*rp]   += gelu_exact(lo + glo) * w2v;
            s[2*rp+1] += gelu_exact(hi + ghi) * w2v;
        }
    }
    #pragma unroll
    for (int rr=0;rr<8;rr++){
        float v = s[rr];
        #pragma unroll
        for (int o=16;o>0;o>>=1) v += __shfl_xor_sync(0xFFFFFFFFu, v, o);
        s[rr] = v;
    }
    if (lane == 0){
        #pragma unroll
        for (int rr=0;rr<8;rr++)
            g_score[rbase + rr] = tanhf(s[rr]);
    }
}

// ---------------- K4a: zero ind ----------------
__global__ void zero_ind_kernel(){
    int i = blockIdx.x*256 + threadIdx.x;
    if (i < BF*TOPK*NSP) g_ind[i] = 0.f;
}

// ---------------- K4: top-49 selection via exact 40-bit binary search ----------------
__global__ void select_kernel(const float* __restrict__ noise){
    __shared__ float sps[NSP];
    int bf = blockIdx.x >> 5;
    int sg = blockIdx.x & 31;
    int wid = threadIdx.x >> 5, lane = threadIdx.x & 31;
    int s = sg*8 + wid;
    if (threadIdx.x < NSP) sps[threadIdx.x] = g_score[bf*NSP + threadIdx.x];
    __syncthreads();
    const float* np = noise + (size_t)(bf*NS + s)*NSP;

    u64 K[7];
    #pragma unroll
    for (int c=0;c<7;c++){
        int l = c*32 + lane;
        u64 kk = 0ull;
        if (l < NSP){
            float p = sps[l] + SIGMA * np[l];
            unsigned u = __float_as_uint(p);
            u ^= (u & 0x80000000u) ? 0xFFFFFFFFu : 0x80000000u;     // monotone key
            kk = ((u64)u << 8) | (unsigned)(255 - l);               // tie: lower l wins
        }
        K[c] = kk;
    }
    // binary search the 49th-largest key (keys distinct, invalid = 0 never selected)
    u64 pref = 0ull;
    #pragma unroll 1
    for (int b=39;b>=0;b--){
        u64 cand = pref | (1ull << b);
        unsigned cnt = 0;
        #pragma unroll
        for (int c=0;c<7;c++) cnt += (K[c] >= cand) ? 1u : 0u;
        cnt = __reduce_add_sync(0xFFFFFFFFu, cnt);
        if (cnt >= TOPK) pref = cand;
    }
    // selected = key >= pref (exactly 49); position = prefix count in l order
    int pre = 0;
    #pragma unroll
    for (int c=0;c<7;c++){
        bool sel = (K[c] >= pref);
        unsigned bal = __ballot_sync(0xFFFFFFFFu, sel);
        int l = c*32 + lane;
        if (sel){
            int k = pre + __popc(bal & ((1u<<lane)-1u));
            atomicAdd(&g_ind[((size_t)bf*TOPK + k)*NSP + l], 1.0f/NS);
        }
        pre += __popc(bal);
    }
}

// ---------------- K5: out = [cls ; ind @ spat] ----------------
__global__ void output_kernel(const float* __restrict__ x, float* __restrict__ out){
    __shared__ float indsT[NSP][TOPK+1];   // 39.2 KB
    int bf = blockIdx.x;
    int d  = blockIdx.y * 128 + threadIdx.x;
    int t  = threadIdx.x;
    #pragma unroll 1
    for (int k=0;k<TOPK;k++)
        for (int l=t; l<NSP; l+=128)
            indsT[l][k] = g_ind[((size_t)bf*TOPK + k)*NSP + l];
    for (int l=t; l<NSP; l+=128) indsT[l][TOPK] = 0.f;
    __syncthreads();

    u64 acc[25];
    #pragma unroll
    for (int kp=0;kp<25;kp++) acc[kp] = 0ull;
    const float* xb = x + (size_t)(bf*NTOK)*DIM + d;
    #pragma unroll 1
    for (int l=0;l<NSP;l++){
        float xv = xb[(size_t)(l+1)*DIM];
        u64 x2 = pk2(xv, xv);
        const u64* row = (const u64*)indsT[l];
        #pragma unroll
        for (int kp=0;kp<25;kp++) ffma2(acc[kp], x2, row[kp]);
    }
    float* ob = out + (size_t)(bf*(1+TOPK))*DIM + d;
    ob[0] = xb[0];   // cls passthrough
    #pragma unroll
    for (int kp=0;kp<25;kp++){
        float lo, hi;
        upk2(acc[kp], lo, hi);
        ob[(size_t)(2*kp+1)*DIM] = lo;
        if (kp < 24) ob[(size_t)(2*kp+2)*DIM] = hi;
    }
}

// ---------------- launcher ----------------
extern "C" void kernel_launch(void* const* d_in, const int* in_sizes, int n_in,
                              void* d_out, int out_size){
    const float* x     = (const float*)d_in[0];
    const float* noise = (const float*)d_in[1];
    const float* gamma = (const float*)d_in[2];
    const float* beta  = (const float*)d_in[3];
    const float* w_in  = (const float*)d_in[4];
    const float* w1    = (const float*)d_in[5];
    const float* w2    = (const float*)d_in[6];
    float* out = (float*)d_out;

    stats_kernel<<<(M1+7)/8, 256>>>(x);
    gemm1_kernel<<<(M1+127)/128, 512>>>(x, gamma, beta, w_in);
    gc_kernel<<<BF, 256>>>(w1);
    score_kernel<<<M3/128, 512>>>(w1, w2);
    zero_ind_kernel<<<(BF*TOPK*NSP + 255)/256, 256>>>();
    select_kernel<<<BF*32, 256>>>(noise);
    dim3 g5(BF, 4);
    output_kernel<<<g5, 128>>>(x, out);
}